// round 15
// baseline (speedup 1.0000x reference)
#include <cuda_runtime.h>
#include <cuda_bf16.h>
#include <cstdint>

#define NN 512

// ---------------- scratch (no allocations allowed) ----------------
__device__ float g_Achunk[NN * 256];   // A projection, chunked [it][kc][128r x 64k]
__device__ float g_B[NN * 256];
__device__ float g_S2p[4][NN * 256];   // partials: [half*2+wm][j*256+n]
// Wf2 split bf16 hi/lo, chunked [kc][...] with SW-XOR pre-applied (bulk-copy ready)
__device__ uint4 g_Whi4[8192];
__device__ uint4 g_Wlo4[8192];

// ================= helpers =================
__device__ __forceinline__ uint32_t smem_u32(const void* p) {
    uint32_t a;
    asm("{ .reg .u64 t; cvta.to.shared.u64 t, %1; cvt.u32.u64 %0, t; }" : "=r"(a) : "l"(p));
    return a;
}

__device__ __forceinline__ void ldsm4(uint32_t (&r)[4], uint32_t addr) {
    asm volatile("ldmatrix.sync.aligned.m8n8.x4.shared.b16 {%0,%1,%2,%3}, [%4];"
        : "=r"(r[0]), "=r"(r[1]), "=r"(r[2]), "=r"(r[3]) : "r"(addr));
}

__device__ __forceinline__ void mma16816(float (&d)[4], const uint32_t (&a)[4],
                                         uint32_t b0, uint32_t b1) {
    asm volatile(
        "mma.sync.aligned.m16n8k16.row.col.f32.bf16.bf16.f32 "
        "{%0,%1,%2,%3}, {%4,%5,%6,%7}, {%8,%9}, {%0,%1,%2,%3};"
        : "+f"(d[0]), "+f"(d[1]), "+f"(d[2]), "+f"(d[3])
        : "r"(a[0]), "r"(a[1]), "r"(a[2]), "r"(a[3]), "r"(b0), "r"(b1));
}

__device__ __forceinline__ uint32_t pack_rn2(float f0, float f1) {
    uint32_t r; asm("cvt.rn.bf16x2.f32 %0, %1, %2;" : "=r"(r) : "f"(f1), "f"(f0));
    return r;
}

// ---- bulk copy + mbarrier ----
#define CP_BULK(dstS, srcG, bytes, mbar) \
    asm volatile("cp.async.bulk.shared::cta.global.mbarrier::complete_tx::bytes [%0], [%1], %2, [%3];" \
        :: "r"((uint32_t)(dstS)), "l"(srcG), "r"((uint32_t)(bytes)), "r"((uint32_t)(mbar)) : "memory")
#define MBARRIER_INIT(mbar, count) \
    asm volatile("mbarrier.init.shared.b64 [%0], %1;" :: "r"((uint32_t)(mbar)), "r"((uint32_t)(count)) : "memory")
#define MBARRIER_EXPECT_TX(mbar, bytes) \
    asm volatile("mbarrier.arrive.expect_tx.shared.b64 _, [%0], %1;" \
        :: "r"((uint32_t)(mbar)), "r"((uint32_t)(bytes)) : "memory")
#define MBARRIER_WAIT_PARITY(mbar_smem_addr, phase_parity) do { \
    uint32_t _mbar = (uint32_t)(mbar_smem_addr); \
    uint32_t _parity = (uint32_t)(phase_parity); \
    uint32_t _done; \
    asm volatile( \
        "{\n\t.reg .pred p;\n\t" \
        "mbarrier.try_wait.parity.acquire.cta.shared::cta.b64 p, [%1], %2;\n\t" \
        "selp.b32 %0, 1, 0, p;\n\t}" \
        : "=r"(_done) : "r"(_mbar), "r"(_parity) : "memory"); \
    if (!_done) { \
        asm volatile( \
            "{\n\t.reg .pred P1;\n\t" \
            "WAIT_LOOP_%=:\n\t" \
            "mbarrier.try_wait.parity.acquire.cta.shared::cta.b64 P1, [%0], %1, 0x989680;\n\t" \
            "@P1 bra.uni WAIT_DONE_%=;\n\t" \
            "bra.uni WAIT_LOOP_%=;\n\t" \
            "WAIT_DONE_%=:\n\t}" \
            :: "r"(_mbar), "r"(_parity) : "memory"); \
    } \
} while(0)

// ================= pair kernel smem layout (byte offsets) =================
#define OFF_WHI 0u         // 2 x 32768
#define OFF_WLO 65536u     // 2 x 32768
#define OFF_AHI 131072u    // 2 x 16384 (split hi, swizzled)
#define OFF_ALO 163840u    // 2 x 16384
#define OFF_RAW 196608u    // 1 x 32768 (raw A fp32, chunk row-major)
#define OFF_BB  229376u    // 2 x 1024 (B[j]+bf1, double-buffered per unit)
#define OFF_MB  231424u    // 3 mbarriers: mbA, mbW0, mbW1
#define PAIR_DYN_SMEM (231456u + 128u)

// ---------------- persistent pairwise HMMA kernel ----------------
// 148 CTAs, each streams units u = bid, bid+148, ... < 1024 (j = u&511, half = u>>9).
__global__ __launch_bounds__(256, 1) void pair_mma_kernel(
    const float* __restrict__ Bm,
    const float* __restrict__ bf1, const float* __restrict__ bf2)
{
    extern __shared__ __align__(16) char smraw[];
    const uint32_t raw0 = smem_u32(smraw);
    const uint32_t sb = (raw0 + 127u) & ~127u;
    char* smp = smraw + (sb - raw0);

    const int bid = blockIdx.x;
    const int t = threadIdx.x;
    const int lane = t & 31;
    const int w = t >> 5;
    const int wm = w >> 2;
    const int wn = w & 3;

    int nu = 0;
    for (int uu = bid; uu < 1024; uu += 148) nu++;
    if (nu == 0) return;
    const int nchunks = nu * 8;

    float* sBB = (float*)(smp + OFF_BB);     // 2 x 256 floats
    const uint32_t mbA  = sb + OFF_MB + 0;
    const uint32_t mbW0 = sb + OFF_MB + 8;
    const uint32_t mbW1 = sb + OFF_MB + 16;

    sBB[t] = Bm[(bid & 511) * 256 + t] + bf1[t];
    if (t == 0) {
        MBARRIER_INIT(mbA, 1);
        MBARRIER_INIT(mbW0, 1); MBARRIER_INIT(mbW1, 1);
    }

    const uint32_t lx = (uint32_t)(lane & 7) * 16u;
    const uint32_t rowOff = (uint32_t)(lane & 15) * 128u;
    const uint32_t segOff = (uint32_t)(lane >> 4) * 16u;
    const uint32_t wmOff = (uint32_t)(wm * 64) * 128u + rowOff;
    const uint32_t wnOff = (uint32_t)(wn * 64) * 128u + rowOff;

    float s[16];
#pragma unroll
    for (int q = 0; q < 16; q++) s[q] = 0.f;

    float acc[4][8][4];
#pragma unroll
    for (int mt = 0; mt < 4; mt++)
#pragma unroll
        for (int nt = 0; nt < 8; nt++)
#pragma unroll
            for (int e = 0; e < 4; e++) acc[mt][nt][e] = 0.f;

    uint32_t ap = 0, wp0 = 0, wp1 = 0;

#define STAGE_BULKS(cx_) do { \
        const int c_ = (cx_) & 7; \
        const int u_ = bid + ((cx_) >> 3) * 148; \
        const int kc_ = c_ & 3; \
        const int it_ = (u_ >> 9) * 2 + (c_ >> 2); \
        const int wb_ = (cx_) & 1; \
        const uint32_t mbw_ = wb_ ? mbW1 : mbW0; \
        MBARRIER_EXPECT_TX(mbA, 32768u); \
        CP_BULK(sb + OFF_RAW, (const void*)(g_Achunk + (it_ * 4 + kc_) * 8192), 32768u, mbA); \
        MBARRIER_EXPECT_TX(mbw_, 65536u); \
        CP_BULK(sb + OFF_WHI + (uint32_t)wb_ * 32768u, (const void*)(g_Whi4 + kc_ * 2048), 32768u, mbw_); \
        CP_BULK(sb + OFF_WLO + (uint32_t)wb_ * 32768u, (const void*)(g_Wlo4 + kc_ * 2048), 32768u, mbw_); \
    } while (0)

    // one vectorized convert iteration r (of 4): 8 floats/thread, STS.128
#define CONV_ONE(r_) do { \
        const int li = (r_) * 256 + t;            /* 0..1023 */ \
        const int row_ = li >> 3, sp_ = li & 7;   /* row, seg-pair */ \
        float4 v0 = *(const float4*)(rawp + li * 8); \
        float4 v1 = *(const float4*)(rawp + li * 8 + 4); \
        float4 b0 = *(const float4*)(bbp + sp_ * 8); \
        float4 b1 = *(const float4*)(bbp + sp_ * 8 + 4); \
        float f0 = fmaxf(v0.x + b0.x, 0.f), f1 = fmaxf(v0.y + b0.y, 0.f); \
        float f2 = fmaxf(v0.z + b0.z, 0.f), f3 = fmaxf(v0.w + b0.w, 0.f); \
        float f4 = fmaxf(v1.x + b1.x, 0.f), f5 = fmaxf(v1.y + b1.y, 0.f); \
        float f6 = fmaxf(v1.z + b1.z, 0.f), f7 = fmaxf(v1.w + b1.w, 0.f); \
        uint4 hp, lp; \
        hp.x = pack_rn2(f0, f1); hp.y = pack_rn2(f2, f3); \
        hp.z = pack_rn2(f4, f5); hp.w = pack_rn2(f6, f7); \
        lp.x = pack_rn2(f0 - __uint_as_float(hp.x << 16), \
                        f1 - __uint_as_float(hp.x & 0xFFFF0000u)); \
        lp.y = pack_rn2(f2 - __uint_as_float(hp.y << 16), \
                        f3 - __uint_as_float(hp.y & 0xFFFF0000u)); \
        lp.z = pack_rn2(f4 - __uint_as_float(hp.z << 16), \
                        f5 - __uint_as_float(hp.z & 0xFFFF0000u)); \
        lp.w = pack_rn2(f6 - __uint_as_float(hp.w << 16), \
                        f7 - __uint_as_float(hp.w & 0xFFFF0000u)); \
        const uint32_t off_ = (uint32_t)(row_ * 128 + sp_ * 16); \
        const uint32_t sw = off_ ^ ((uint32_t)(row_ & 7) * 16u); \
        *(uint4*)(aHi + sw) = hp; \
        *(uint4*)(aLo + sw) = lp; \
    } while (0)

    // ---- prologue: stage chunk 0, convert into split[0]
    __syncthreads();
    if (t == 0) STAGE_BULKS(0);
    MBARRIER_WAIT_PARITY(mbA, ap); ap ^= 1;
    {
        const float* rawp = (const float*)(smp + OFF_RAW);
        char* aHi = smp + OFF_AHI;
        char* aLo = smp + OFF_ALO;
        const float* bbp = sBB + 0;
#pragma unroll
        for (int r = 0; r < 4; r++) CONV_ONE(r);
    }
    MBARRIER_WAIT_PARITY(mbW0, wp0); wp0 ^= 1;
    __syncthreads();

    // ---- continuous chunk stream across all units
#pragma unroll 1
    for (int ci = 0; ci < nchunks; ci++) {
        const int c = ci & 7;
        const int ui = ci >> 3;
        const int b = ci & 1;
        const bool cvt = (ci + 1 < nchunks);

        if (cvt && t == 0) STAGE_BULKS(ci + 1);

        if (c == 0 && ui + 1 < nu) {
            const int jn = (bid + (ui + 1) * 148) & 511;
            sBB[((ui + 1) & 1) * 256 + t] = Bm[jn * 256 + t] + bf1[t];
        }

        const float* rawp = (const float*)(smp + OFF_RAW);
        char* aHi = smp + OFF_AHI + (uint32_t)(b ^ 1) * 16384u;
        char* aLo = smp + OFF_ALO + (uint32_t)(b ^ 1) * 16384u;
        const int ci2 = ci + 1;
        const float* bbp = sBB + ((ci2 >> 3) & 1) * 256 + ((ci2 & 3) * 64);

        {
            const uint32_t aRowHi = sb + OFF_AHI + (uint32_t)b * 16384u + wmOff;
            const uint32_t aRowLo = sb + OFF_ALO + (uint32_t)b * 16384u + wmOff;
            const uint32_t wRowHi = sb + OFF_WHI + (uint32_t)b * 32768u + wnOff;
            const uint32_t wRowLo = sb + OFF_WLO + (uint32_t)b * 32768u + wnOff;
#pragma unroll
            for (int ks = 0; ks < 4; ks++) {
                const uint32_t kx = ((uint32_t)(ks * 32) + segOff) ^ lx;
                uint32_t aH[4][4], aL[4][4], wf[4][4];
                // front-load all A fragments + W-hi: aL latency hides under pass 1
#pragma unroll
                for (int mt = 0; mt < 4; mt++) ldsm4(aH[mt], aRowHi + mt * 2048 + kx);
#pragma unroll
                for (int np = 0; np < 4; np++) ldsm4(wf[np], wRowHi + np * 2048 + kx);
#pragma unroll
                for (int mt = 0; mt < 4; mt++) ldsm4(aL[mt], aRowLo + mt * 2048 + kx);
                // pass 1: aH * wH
#pragma unroll
                for (int mt = 0; mt < 4; mt++)
#pragma unroll
                    for (int np = 0; np < 4; np++) {
                        mma16816(acc[mt][2 * np],     aH[mt], wf[np][0], wf[np][2]);
                        mma16816(acc[mt][2 * np + 1], aH[mt], wf[np][1], wf[np][3]);
                    }
                if (ks == 1 && cvt) { MBARRIER_WAIT_PARITY(mbA, ap); ap ^= 1; CONV_ONE(0); }
                if (ks == 2 && cvt) { CONV_ONE(2); }
                // pass 2: aL * wH
#pragma unroll
                for (int mt = 0; mt < 4; mt++)
#pragma unroll
                    for (int np = 0; np < 4; np++) {
                        mma16816(acc[mt][2 * np],     aL[mt], wf[np][0], wf[np][2]);
                        mma16816(acc[mt][2 * np + 1], aL[mt], wf[np][1], wf[np][3]);
                    }
                if (ks == 1 && cvt) { CONV_ONE(1); }
                if (ks == 2 && cvt) { CONV_ONE(3); }
                // load W-lo, pass 3: aH * wL
#pragma unroll
                for (int np = 0; np < 4; np++) ldsm4(wf[np], wRowLo + np * 2048 + kx);
#pragma unroll
                for (int mt = 0; mt < 4; mt++)
#pragma unroll
                    for (int np = 0; np < 4; np++) {
                        mma16816(acc[mt][2 * np],     aH[mt], wf[np][0], wf[np][2]);
                        mma16816(acc[mt][2 * np + 1], aH[mt], wf[np][1], wf[np][3]);
                    }
            }
        }

        // ---- i-tile boundary: fold relu(h2 + bf2) into running sums
        if ((c & 3) == 3) {
#pragma unroll
            for (int nt = 0; nt < 8; nt++) {
                const int col = wn * 64 + nt * 8 + (lane & 3) * 2;
                const float b20 = bf2[col], b21 = bf2[col + 1];
                float t0 = 0.f, t1 = 0.f;
#pragma unroll
                for (int mt = 0; mt < 4; mt++) {
                    t0 += fmaxf(acc[mt][nt][0] + b20, 0.f) + fmaxf(acc[mt][nt][2] + b20, 0.f);
                    t1 += fmaxf(acc[mt][nt][1] + b21, 0.f) + fmaxf(acc[mt][nt][3] + b21, 0.f);
                    acc[mt][nt][0] = 0.f; acc[mt][nt][1] = 0.f;
                    acc[mt][nt][2] = 0.f; acc[mt][nt][3] = 0.f;
                }
                s[nt * 2]     += t0;
                s[nt * 2 + 1] += t1;
            }
        }

        // ---- unit epilogue: reduce within warp, write per-wm partials, reset s
        if (c == 7) {
            const int u = bid + ui * 148;
            const int j = u & 511, half = u >> 9;
#pragma unroll
            for (int q = 0; q < 16; q++) {
                s[q] += __shfl_xor_sync(0xFFFFFFFFu, s[q], 4);
                s[q] += __shfl_xor_sync(0xFFFFFFFFu, s[q], 8);
                s[q] += __shfl_xor_sync(0xFFFFFFFFu, s[q], 16);
            }
            if (lane < 4) {
                float* dst = g_S2p[half * 2 + wm] + j * 256;
#pragma unroll
                for (int nt = 0; nt < 8; nt++) {
                    const int col = wn * 64 + nt * 8 + lane * 2;
                    dst[col]     = s[nt * 2];
                    dst[col + 1] = s[nt * 2 + 1];
                }
            }
#pragma unroll
            for (int q = 0; q < 16; q++) s[q] = 0.f;
        }

        if (cvt) {
            if (ci2 & 1) { MBARRIER_WAIT_PARITY(mbW1, wp1); wp1 ^= 1; }
            else         { MBARRIER_WAIT_PARITY(mbW0, wp0); wp0 ^= 1; }
        }
        __syncthreads();
    }
}

// ---------------- fused prep: Wf2 split (pre-swizzled) + A/B projection ----------------
__global__ __launch_bounds__(256) void prep_ab_kernel(
    const float* __restrict__ hid, const float* __restrict__ Wf1,
    const float* __restrict__ Wf2)
{
    __shared__ float sX[32][34];
    __shared__ float sW[32][34];
    const int bid = blockIdx.x;
    const int t = threadIdx.x;

    if (bid < 256) {
        const int idx = bid * 256 + t;
        const int n = idx >> 8, k = idx & 255;
        const float v = Wf2[idx];
        const __nv_bfloat16 hb = __float2bfloat16(v);
        const float lf = v - __bfloat162float(hb);
        const int kc = k >> 6, kk = k & 63;
        const int seg = kk >> 3, e = kk & 7;
        const int o = kc * 16384 + n * 64 + ((seg ^ (n & 7)) << 3) + e;
        ((__nv_bfloat16*)g_Whi4)[o] = hb;
        ((__nv_bfloat16*)g_Wlo4)[o] = __float2bfloat16(lf);
        return;
    }

    const int b = bid - 256;
    const int z = b >> 7;
    const int rem = b & 127;
    const int m0 = (rem >> 3) * 32;
    const int n0 = (rem & 7) * 32;
    const float* W = Wf1 + z * 128;

    const int lm = t >> 3;
    const int lk = (t & 7) * 4;
    const int tm = (t >> 4) * 2;
    const int tn = (t & 15) * 2;

    float a00 = 0.f, a01 = 0.f, a10 = 0.f, a11 = 0.f;
    float4 xv = *(const float4*)(hid + (m0 + lm) * 128 + lk);
    float4 wv = *(const float4*)(W + (n0 + lm) * 256 + lk);

    for (int c = 0; c < 4; c++) {
        __syncthreads();
        sX[lk + 0][lm] = xv.x; sX[lk + 1][lm] = xv.y;
        sX[lk + 2][lm] = xv.z; sX[lk + 3][lm] = xv.w;
        sW[lk + 0][lm] = wv.x; sW[lk + 1][lm] = wv.y;
        sW[lk + 2][lm] = wv.z; sW[lk + 3][lm] = wv.w;
        __syncthreads();
        if (c < 3) {
            const int ko = (c + 1) * 32 + lk;
            xv = *(const float4*)(hid + (m0 + lm) * 128 + ko);
            wv = *(const float4*)(W + (n0 + lm) * 256 + ko);
        }
#pragma unroll
        for (int kk = 0; kk < 32; kk++) {
            float2 avv = *(const float2*)&sX[kk][tm];
            float2 bvv = *(const float2*)&sW[kk][tn];
            a00 = fmaf(avv.x, bvv.x, a00);
            a01 = fmaf(avv.x, bvv.y, a01);
            a10 = fmaf(avv.y, bvv.x, a10);
            a11 = fmaf(avv.y, bvv.y, a11);
        }
    }
    const int m = m0 + tm, n = n0 + tn;
    if (z == 0) {
#define AIDX(m_, n_) ((((m_) >> 7) * 4 + ((n_) >> 6)) * 8192 + ((m_) & 127) * 64 + ((n_) & 63))
        g_Achunk[AIDX(m, n)]         = a00;
        g_Achunk[AIDX(m, n + 1)]     = a01;
        g_Achunk[AIDX(m + 1, n)]     = a10;
        g_Achunk[AIDX(m + 1, n + 1)] = a11;
#undef AIDX
    } else {
        g_B[m * 256 + n] = a00;       g_B[m * 256 + n + 1] = a01;
        g_B[(m + 1) * 256 + n] = a10; g_B[(m + 1) * 256 + n + 1] = a11;
    }
}

// ---------------- fused tail: coalesced warp-split layers ----------------
template<int K, int N, int ACT>
__device__ __forceinline__ void wlayer(
    const float* __restrict__ Xs, const float* __restrict__ W,
    const float* __restrict__ bias, float bscale,
    float* __restrict__ Ys, int w, int ng, int kl)
{
#pragma unroll
    for (int it = 0; it < N / 32; it++) {
        const int n = it * 32 + w * 4 + ng;
        const float* wr = W + n * K + kl * 4;
        float a0 = 0.f, a1 = 0.f, a2 = 0.f, a3 = 0.f;
#pragma unroll
        for (int jj = 0; jj < K / 32; jj++) {
            const int k = kl * 4 + jj * 32;
            const float4 wv = *(const float4*)(wr + jj * 32);
            const float4 x0 = *(const float4*)(Xs + 0 * 512 + k);
            const float4 x1 = *(const float4*)(Xs + 1 * 512 + k);
            const float4 x2 = *(const float4*)(Xs + 2 * 512 + k);
            const float4 x3 = *(const float4*)(Xs + 3 * 512 + k);
            a0 += wv.x * x0.x + wv.y * x0.y + wv.z * x0.z + wv.w * x0.w;
            a1 += wv.x * x1.x + wv.y * x1.y + wv.z * x1.z + wv.w * x1.w;
            a2 += wv.x * x2.x + wv.y * x2.y + wv.z * x2.z + wv.w * x2.w;
            a3 += wv.x * x3.x + wv.y * x3.y + wv.z * x3.z + wv.w * x3.w;
        }
#pragma unroll
        for (int m = 1; m < 8; m <<= 1) {
            a0 += __shfl_xor_sync(0xFFFFFFFFu, a0, m);
            a1 += __shfl_xor_sync(0xFFFFFFFFu, a1, m);
            a2 += __shfl_xor_sync(0xFFFFFFFFu, a2, m);
            a3 += __shfl_xor_sync(0xFFFFFFFFu, a3, m);
        }
        if (kl == 0) {
            const float bb = bscale * bias[n];
            float v0 = a0 + bb, v1 = a1 + bb, v2 = a2 + bb, v3 = a3 + bb;
            if (ACT) {
                v0 = fmaxf(v0, 0.f); v1 = fmaxf(v1, 0.f);
                v2 = fmaxf(v2, 0.f); v3 = fmaxf(v3, 0.f);
            }
            Ys[0 * 512 + n] = v0; Ys[1 * 512 + n] = v1;
            Ys[2 * 512 + n] = v2; Ys[3 * 512 + n] = v3;
        }
    }
}

__device__ __forceinline__ void wlayer_gates(
    const float* __restrict__ Xs,
    const float* __restrict__ Wih, const float* __restrict__ Whh,
    const float* __restrict__ bih, const float* __restrict__ bhh,
    float* __restrict__ Ys, int w, int ng, int kl)
{
#pragma unroll
    for (int it = 0; it < 16; it++) {
        const int n = it * 32 + w * 4 + ng;
        float a0 = 0.f, a1 = 0.f, a2 = 0.f, a3 = 0.f;
#pragma unroll
        for (int jj = 0; jj < 8; jj++) {
            const int k = kl * 4 + jj * 32;
            const int wk = k & 127;
            const float* base = (jj < 4) ? Wih : Whh;
            const float4 wv = *(const float4*)(base + n * 128 + wk);
            const float4 x0 = *(const float4*)(Xs + 0 * 512 + k);
            const float4 x1 = *(const float4*)(Xs + 1 * 512 + k);
            const float4 x2 = *(const float4*)(Xs + 2 * 512 + k);
            const float4 x3 = *(const float4*)(Xs + 3 * 512 + k);
            a0 += wv.x * x0.x + wv.y * x0.y + wv.z * x0.z + wv.w * x0.w;
            a1 += wv.x * x1.x + wv.y * x1.y + wv.z * x1.z + wv.w * x1.w;
            a2 += wv.x * x2.x + wv.y * x2.y + wv.z * x2.z + wv.w * x2.w;
            a3 += wv.x * x3.x + wv.y * x3.y + wv.z * x3.z + wv.w * x3.w;
        }
#pragma unroll
        for (int m = 1; m < 8; m <<= 1) {
            a0 += __shfl_xor_sync(0xFFFFFFFFu, a0, m);
            a1 += __shfl_xor_sync(0xFFFFFFFFu, a1, m);
            a2 += __shfl_xor_sync(0xFFFFFFFFu, a2, m);
            a3 += __shfl_xor_sync(0xFFFFFFFFu, a3, m);
        }
        if (kl == 0) {
            const float bb = bih[n] + bhh[n];
            Ys[0 * 512 + n] = a0 + bb; Ys[1 * 512 + n] = a1 + bb;
            Ys[2 * 512 + n] = a2 + bb; Ys[3 * 512 + n] = a3 + bb;
        }
    }
}

__global__ __launch_bounds__(256) void tail_kernel(
    const float* __restrict__ x,   const float* __restrict__ h0,
    const float* __restrict__ c0,
    const float* __restrict__ Wf3, const float* __restrict__ bf3,
    const float* __restrict__ Wg1, const float* __restrict__ bg1,
    const float* __restrict__ Wg2, const float* __restrict__ bg2,
    const float* __restrict__ Wg3, const float* __restrict__ bg3,
    const float* __restrict__ W_ih, const float* __restrict__ W_hh,
    const float* __restrict__ b_ih, const float* __restrict__ b_hh,
    const float* __restrict__ Wo1, const float* __restrict__ bo1,
    const float* __restrict__ Wo2, const float* __restrict__ bo2,
    float* __restrict__ out)
{
    __shared__ float Xa[4 * 512];
    __shared__ float Xb[4 * 512];
    const int t = threadIdx.x;
    const int w = t >> 5, lane = t & 31;
    const int ng = lane >> 3, kl = lane & 7;
    const int r0 = blockIdx.x * 4;

#pragma unroll
    for (int r = 0; r < 4; r++) {
        const int gi = (r0 + r) * 256 + t;
        Xa[r * 512 + t] = g_S2p[0][gi] + g_S2p[1][gi] + g_S2p[2][gi] + g_S2p[3][gi];
    }
    __syncthreads();

#pragma unroll
    for (int q = 0; q < 2; q++) {
        const int item = q * 256 + t;
        const int r = item >> 7, k = item & 127;
        Xb[r * 512 + k] = x[(r0 + r) * 128 + k];
    }
    wlayer<256, 128, 0>(Xa, Wf3, bf3, 512.f, Xb + 128, w, ng, kl);
    __syncthreads();

    wlayer<256, 256, 1>(Xb, Wg1, bg1, 1.f, Xa, w, ng, kl);
    __syncthreads();

    wlayer<256, 256, 1>(Xa, Wg2, bg2, 1.f, Xb, w, ng, kl);
    __syncthreads();

#pragma unroll
    for (int q = 0; q < 2; q++) {
        const int item = q * 256 + t;
        const int r = item >> 7, k = item & 127;
        Xa[r * 512 + 128 + k] = h0[(r0 + r) * 128 + k];
    }
    wlayer<256, 128, 0>(Xb, Wg3, bg3, 1.f, Xa, w, ng, kl);
    __syncthreads();

    wlayer_gates(Xa, W_ih, W_hh, b_ih, b_hh, Xb, w, ng, kl);
    __syncthreads();

#pragma unroll
    for (int q = 0; q < 2; q++) {
        const int item = q * 256 + t;
        const int r = item >> 7, h = item & 127;
        const float* g = Xb + r * 512;
        const float ig = 1.f / (1.f + expf(-g[h]));
        const float fg = 1.f / (1.f + expf(-g[128 + h]));
        const float gg = tanhf(g[256 + h]);
        const float og = 1.f / (1.f + expf(-g[384 + h]));
        const int gi = (r0 + r) * 128 + h;
        const float c = fg * c0[gi] + ig * gg;
        const float hn = og * tanhf(c);
        Xa[r * 512 + h] = hn;
        out[32768 + gi]  = hn;
        out[98304 + gi]  = hn;
        out[163840 + gi] = c;
    }
    __syncthreads();

    wlayer<128, 256, 1>(Xa, Wo1, bo1, 1.f, Xb, w, ng, kl);
    __syncthreads();

#pragma unroll
    for (int it = 0; it < 2; it++) {
        const int n = it * 32 + w * 4 + ng;
        const float* wr = Wo2 + n * 256 + kl * 4;
        float a0 = 0.f, a1 = 0.f, a2 = 0.f, a3 = 0.f;
#pragma unroll
        for (int jj = 0; jj < 8; jj++) {
            const int k = kl * 4 + jj * 32;
            const float4 wv = *(const float4*)(wr + jj * 32);
            const float4 x0 = *(const float4*)(Xb + 0 * 512 + k);
            const float4 x1 = *(const float4*)(Xb + 1 * 512 + k);
            const float4 x2 = *(const float4*)(Xb + 2 * 512 + k);
            const float4 x3 = *(const float4*)(Xb + 3 * 512 + k);
            a0 += wv.x * x0.x + wv.y * x0.y + wv.z * x0.z + wv.w * x0.w;
            a1 += wv.x * x1.x + wv.y * x1.y + wv.z * x1.z + wv.w * x1.w;
            a2 += wv.x * x2.x + wv.y * x2.y + wv.z * x2.z + wv.w * x2.w;
            a3 += wv.x * x3.x + wv.y * x3.y + wv.z * x3.z + wv.w * x3.w;
        }
#pragma unroll
        for (int m = 1; m < 8; m <<= 1) {
            a0 += __shfl_xor_sync(0xFFFFFFFFu, a0, m);
            a1 += __shfl_xor_sync(0xFFFFFFFFu, a1, m);
            a2 += __shfl_xor_sync(0xFFFFFFFFu, a2, m);
            a3 += __shfl_xor_sync(0xFFFFFFFFu, a3, m);
        }
        if (kl == 0) {
            const float bb = bo2[n];
            out[(r0 + 0) * 64 + n] = a0 + bb;
            out[(r0 + 1) * 64 + n] = a1 + bb;
            out[(r0 + 2) * 64 + n] = a2 + bb;
            out[(r0 + 3) * 64 + n] = a3 + bb;
        }
    }
}

// ---------------- launch ----------------
extern "C" void kernel_launch(void* const* d_in, const int* in_sizes, int n_in,
                              void* d_out, int out_size)
{
    const float* x    = (const float*)d_in[0];
    const float* hid  = (const float*)d_in[1];
    const float* h0   = (const float*)d_in[2];
    const float* c0   = (const float*)d_in[3];
    const float* Wf1  = (const float*)d_in[4];
    const float* bf1  = (const float*)d_in[5];
    const float* Wf2  = (const float*)d_in[6];
    const float* bf2  = (const float*)d_in[7];
    const float* Wf3  = (const float*)d_in[8];
    const float* bf3  = (const float*)d_in[9];
    const float* Wg1  = (const float*)d_in[10];
    const float* bg1  = (const float*)d_in[11];
    const float* Wg2  = (const float*)d_in[12];
    const float* bg2  = (const float*)d_in[13];
    const float* Wg3  = (const float*)d_in[14];
    const float* bg3  = (const float*)d_in[15];
    const float* W_ih = (const float*)d_in[16];
    const float* W_hh = (const float*)d_in[17];
    const float* b_ih = (const float*)d_in[18];
    const float* b_hh = (const float*)d_in[19];
    const float* Wo1  = (const float*)d_in[20];
    const float* bo1  = (const float*)d_in[21];
    const float* Wo2  = (const float*)d_in[22];
    const float* bo2  = (const float*)d_in[23];
    float* out = (float*)d_out;

    float* pB;
    cudaGetSymbolAddress((void**)&pB, g_B);

    cudaFuncSetAttribute(pair_mma_kernel, cudaFuncAttributeMaxDynamicSharedMemorySize, PAIR_DYN_SMEM);

    // Wf2 split (pre-swizzled) + A/B projection (A written chunked)
    prep_ab_kernel<<<512, 256>>>(hid, Wf1, Wf2);

    // persistent pair kernel: 148 CTAs stream all 1024 (j,half) units
    pair_mma_kernel<<<148, 256, PAIR_DYN_SMEM>>>(pB, bf1, bf2);

    // fused tail (sums 4 partial arrays)
    tail_kernel<<<128, 256>>>(x, h0, c0, Wf3, bf3, Wg1, bg1, Wg2, bg2, Wg3, bg3,
                              W_ih, W_hh, b_ih, b_hh, Wo1, bo1, Wo2, bo2, out);
}

// round 17
// speedup vs baseline: 1.0476x; 1.0476x over previous
#include <cuda_runtime.h>
#include <cuda_bf16.h>
#include <cstdint>

#define NN 512
#define NCTA 148

// ---------------- scratch (no allocations allowed) ----------------
__device__ float g_Achunk[NN * 256];   // A projection, chunked [it][kc][128r x 64k]
__device__ float g_B[NN * 256];
__device__ float g_S2p[4][NN * 256];   // partials: [half*2+wm][j*256+n]
__device__ uint4 g_Whi4[8192];         // Wf2 hi bf16, chunked+swizzled
__device__ uint4 g_Wlo4[8192];         // Wf2 lo bf16
__device__ unsigned g_sync1, g_sync2;  // generation-based grid barriers

// ================= helpers =================
__device__ __forceinline__ uint32_t smem_u32(const void* p) {
    uint32_t a;
    asm("{ .reg .u64 t; cvta.to.shared.u64 t, %1; cvt.u32.u64 %0, t; }" : "=r"(a) : "l"(p));
    return a;
}

__device__ __forceinline__ void ldsm4(uint32_t (&r)[4], uint32_t addr) {
    asm volatile("ldmatrix.sync.aligned.m8n8.x4.shared.b16 {%0,%1,%2,%3}, [%4];"
        : "=r"(r[0]), "=r"(r[1]), "=r"(r[2]), "=r"(r[3]) : "r"(addr));
}

__device__ __forceinline__ void mma16816(float (&d)[4], const uint32_t (&a)[4],
                                         uint32_t b0, uint32_t b1) {
    asm volatile(
        "mma.sync.aligned.m16n8k16.row.col.f32.bf16.bf16.f32 "
        "{%0,%1,%2,%3}, {%4,%5,%6,%7}, {%8,%9}, {%0,%1,%2,%3};"
        : "+f"(d[0]), "+f"(d[1]), "+f"(d[2]), "+f"(d[3])
        : "r"(a[0]), "r"(a[1]), "r"(a[2]), "r"(a[3]), "r"(b0), "r"(b1));
}

__device__ __forceinline__ uint32_t pack_rn2(float f0, float f1) {
    uint32_t r; asm("cvt.rn.bf16x2.f32 %0, %1, %2;" : "=r"(r) : "f"(f1), "f"(f0));
    return r;
}

#define CP_BULK(dstS, srcG, bytes, mbar) \
    asm volatile("cp.async.bulk.shared::cta.global.mbarrier::complete_tx::bytes [%0], [%1], %2, [%3];" \
        :: "r"((uint32_t)(dstS)), "l"(srcG), "r"((uint32_t)(bytes)), "r"((uint32_t)(mbar)) : "memory")
#define MBARRIER_INIT(mbar, count) \
    asm volatile("mbarrier.init.shared.b64 [%0], %1;" :: "r"((uint32_t)(mbar)), "r"((uint32_t)(count)) : "memory")
#define MBARRIER_EXPECT_TX(mbar, bytes) \
    asm volatile("mbarrier.arrive.expect_tx.shared.b64 _, [%0], %1;" \
        :: "r"((uint32_t)(mbar)), "r"((uint32_t)(bytes)) : "memory")
#define MBARRIER_WAIT_PARITY(mbar_smem_addr, phase_parity) do { \
    uint32_t _mbar = (uint32_t)(mbar_smem_addr); \
    uint32_t _parity = (uint32_t)(phase_parity); \
    uint32_t _done; \
    asm volatile( \
        "{\n\t.reg .pred p;\n\t" \
        "mbarrier.try_wait.parity.acquire.cta.shared::cta.b64 p, [%1], %2;\n\t" \
        "selp.b32 %0, 1, 0, p;\n\t}" \
        : "=r"(_done) : "r"(_mbar), "r"(_parity) : "memory"); \
    if (!_done) { \
        asm volatile( \
            "{\n\t.reg .pred P1;\n\t" \
            "WAIT_LOOP_%=:\n\t" \
            "mbarrier.try_wait.parity.acquire.cta.shared::cta.b64 P1, [%0], %1, 0x989680;\n\t" \
            "@P1 bra.uni WAIT_DONE_%=;\n\t" \
            "bra.uni WAIT_LOOP_%=;\n\t" \
            "WAIT_DONE_%=:\n\t}" \
            :: "r"(_mbar), "r"(_parity) : "memory"); \
    } \
} while(0)

// generation-based grid barrier: counter never reset (replay-safe).
// fence.proxy.async: order generic-proxy writes (phase N) vs async-proxy
// reads (TMA in phase N+1). __threadfence: device-scope generic ordering.
__device__ __forceinline__ void grid_sync(unsigned* cnt) {
    __syncthreads();
    asm volatile("fence.proxy.async;" ::: "memory");
    if (threadIdx.x == 0) {
        __threadfence();
        unsigned gen = atomicAdd(cnt, 1u);
        unsigned target = (gen / NCTA + 1u) * NCTA;
        unsigned v;
        do {
            asm volatile("ld.volatile.global.u32 %0, [%1];" : "=r"(v) : "l"(cnt));
            if (v < target) __nanosleep(128);
        } while (v < target);
        __threadfence();
        asm volatile("fence.proxy.async;" ::: "memory");
    }
    __syncthreads();
}

// ================= pair-phase smem layout (byte offsets) =================
#define OFF_WHI 0u         // 2 x 32768
#define OFF_WLO 65536u     // 2 x 32768
#define OFF_AHI 131072u    // 2 x 16384 (split hi, swizzled)
#define OFF_ALO 163840u    // 2 x 16384
#define OFF_RAW 196608u    // 1 x 32768 (raw A fp32, chunk row-major)
#define OFF_BB  229376u    // 2 x 1024 (B[j]+bf1, double-buffered per unit)
#define OFF_MB  231424u    // 3 mbarriers: mbA, mbW0, mbW1
#define MEGA_DYN_SMEM (231456u + 128u)

// ---------------- tail layers (device) ----------------
template<int K, int N, int ACT>
__device__ __forceinline__ void wlayer(
    const float* __restrict__ Xs, const float* __restrict__ W,
    const float* __restrict__ bias, float bscale,
    float* __restrict__ Ys, int w, int ng, int kl)
{
#pragma unroll
    for (int it = 0; it < N / 32; it++) {
        const int n = it * 32 + w * 4 + ng;
        const float* wr = W + n * K + kl * 4;
        float a0 = 0.f, a1 = 0.f, a2 = 0.f, a3 = 0.f;
#pragma unroll
        for (int jj = 0; jj < K / 32; jj++) {
            const int k = kl * 4 + jj * 32;
            const float4 wv = *(const float4*)(wr + jj * 32);
            const float4 x0 = *(const float4*)(Xs + 0 * 512 + k);
            const float4 x1 = *(const float4*)(Xs + 1 * 512 + k);
            const float4 x2 = *(const float4*)(Xs + 2 * 512 + k);
            const float4 x3 = *(const float4*)(Xs + 3 * 512 + k);
            a0 += wv.x * x0.x + wv.y * x0.y + wv.z * x0.z + wv.w * x0.w;
            a1 += wv.x * x1.x + wv.y * x1.y + wv.z * x1.z + wv.w * x1.w;
            a2 += wv.x * x2.x + wv.y * x2.y + wv.z * x2.z + wv.w * x2.w;
            a3 += wv.x * x3.x + wv.y * x3.y + wv.z * x3.z + wv.w * x3.w;
        }
#pragma unroll
        for (int m = 1; m < 8; m <<= 1) {
            a0 += __shfl_xor_sync(0xFFFFFFFFu, a0, m);
            a1 += __shfl_xor_sync(0xFFFFFFFFu, a1, m);
            a2 += __shfl_xor_sync(0xFFFFFFFFu, a2, m);
            a3 += __shfl_xor_sync(0xFFFFFFFFu, a3, m);
        }
        if (kl == 0) {
            const float bb = bscale * bias[n];
            float v0 = a0 + bb, v1 = a1 + bb, v2 = a2 + bb, v3 = a3 + bb;
            if (ACT) {
                v0 = fmaxf(v0, 0.f); v1 = fmaxf(v1, 0.f);
                v2 = fmaxf(v2, 0.f); v3 = fmaxf(v3, 0.f);
            }
            Ys[0 * 512 + n] = v0; Ys[1 * 512 + n] = v1;
            Ys[2 * 512 + n] = v2; Ys[3 * 512 + n] = v3;
        }
    }
}

__device__ __forceinline__ void wlayer_gates(
    const float* __restrict__ Xs,
    const float* __restrict__ Wih, const float* __restrict__ Whh,
    const float* __restrict__ bih, const float* __restrict__ bhh,
    float* __restrict__ Ys, int w, int ng, int kl)
{
#pragma unroll
    for (int it = 0; it < 16; it++) {
        const int n = it * 32 + w * 4 + ng;
        float a0 = 0.f, a1 = 0.f, a2 = 0.f, a3 = 0.f;
#pragma unroll
        for (int jj = 0; jj < 8; jj++) {
            const int k = kl * 4 + jj * 32;
            const int wk = k & 127;
            const float* base = (jj < 4) ? Wih : Whh;
            const float4 wv = *(const float4*)(base + n * 128 + wk);
            const float4 x0 = *(const float4*)(Xs + 0 * 512 + k);
            const float4 x1 = *(const float4*)(Xs + 1 * 512 + k);
            const float4 x2 = *(const float4*)(Xs + 2 * 512 + k);
            const float4 x3 = *(const float4*)(Xs + 3 * 512 + k);
            a0 += wv.x * x0.x + wv.y * x0.y + wv.z * x0.z + wv.w * x0.w;
            a1 += wv.x * x1.x + wv.y * x1.y + wv.z * x1.z + wv.w * x1.w;
            a2 += wv.x * x2.x + wv.y * x2.y + wv.z * x2.z + wv.w * x2.w;
            a3 += wv.x * x3.x + wv.y * x3.y + wv.z * x3.z + wv.w * x3.w;
        }
#pragma unroll
        for (int m = 1; m < 8; m <<= 1) {
            a0 += __shfl_xor_sync(0xFFFFFFFFu, a0, m);
            a1 += __shfl_xor_sync(0xFFFFFFFFu, a1, m);
            a2 += __shfl_xor_sync(0xFFFFFFFFu, a2, m);
            a3 += __shfl_xor_sync(0xFFFFFFFFu, a3, m);
        }
        if (kl == 0) {
            const float bb = bih[n] + bhh[n];
            Ys[0 * 512 + n] = a0 + bb; Ys[1 * 512 + n] = a1 + bb;
            Ys[2 * 512 + n] = a2 + bb; Ys[3 * 512 + n] = a3 + bb;
        }
    }
}

// ---------------- mega kernel: prep -> sync -> pair -> sync -> tail ----------------
__global__ __launch_bounds__(256, 1) void mega_kernel(
    const float* __restrict__ x,   const float* __restrict__ hid,
    const float* __restrict__ h0,  const float* __restrict__ c0,
    const float* __restrict__ Wf1, const float* __restrict__ bf1,
    const float* __restrict__ Wf2, const float* __restrict__ bf2,
    const float* __restrict__ Wf3, const float* __restrict__ bf3,
    const float* __restrict__ Wg1, const float* __restrict__ bg1,
    const float* __restrict__ Wg2, const float* __restrict__ bg2,
    const float* __restrict__ Wg3, const float* __restrict__ bg3,
    const float* __restrict__ W_ih, const float* __restrict__ W_hh,
    const float* __restrict__ b_ih, const float* __restrict__ b_hh,
    const float* __restrict__ Wo1, const float* __restrict__ bo1,
    const float* __restrict__ Wo2, const float* __restrict__ bo2,
    float* __restrict__ out)
{
    extern __shared__ __align__(16) char smraw[];
    const uint32_t raw0 = smem_u32(smraw);
    const uint32_t sb = (raw0 + 127u) & ~127u;
    char* smp = smraw + (sb - raw0);

    const int bid = blockIdx.x;
    const int t = threadIdx.x;
    const int lane = t & 31;
    const int w = t >> 5;

    // =============== PHASE 1: prep (512 jobs over 148 CTAs) ===============
    {
        float (*sX)[34] = (float(*)[34])(smp);
        float (*sW)[34] = (float(*)[34])(smp + 4352);
#pragma unroll 1
        for (int job = bid; job < 512; job += NCTA) {
            if (job < 256) {
                const int idx = job * 256 + t;
                const int n = idx >> 8, k = idx & 255;
                const float v = Wf2[idx];
                const __nv_bfloat16 hb = __float2bfloat16(v);
                const float lf = v - __bfloat162float(hb);
                const int kc = k >> 6, kk = k & 63;
                const int seg = kk >> 3, e = kk & 7;
                const int o = kc * 16384 + n * 64 + ((seg ^ (n & 7)) << 3) + e;
                ((__nv_bfloat16*)g_Whi4)[o] = hb;
                ((__nv_bfloat16*)g_Wlo4)[o] = __float2bfloat16(lf);
                continue;
            }
            const int b = job - 256;
            const int z = b >> 7;
            const int rem = b & 127;
            const int m0 = (rem >> 3) * 32;
            const int n0 = (rem & 7) * 32;
            const float* W = Wf1 + z * 128;
            const int lm = t >> 3;
            const int lk = (t & 7) * 4;
            const int tm = (t >> 4) * 2;
            const int tn = (t & 15) * 2;

            float a00 = 0.f, a01 = 0.f, a10 = 0.f, a11 = 0.f;
            float4 xv = *(const float4*)(hid + (m0 + lm) * 128 + lk);
            float4 wv = *(const float4*)(W + (n0 + lm) * 256 + lk);
            for (int c = 0; c < 4; c++) {
                __syncthreads();
                sX[lk + 0][lm] = xv.x; sX[lk + 1][lm] = xv.y;
                sX[lk + 2][lm] = xv.z; sX[lk + 3][lm] = xv.w;
                sW[lk + 0][lm] = wv.x; sW[lk + 1][lm] = wv.y;
                sW[lk + 2][lm] = wv.z; sW[lk + 3][lm] = wv.w;
                __syncthreads();
                if (c < 3) {
                    const int ko = (c + 1) * 32 + lk;
                    xv = *(const float4*)(hid + (m0 + lm) * 128 + ko);
                    wv = *(const float4*)(W + (n0 + lm) * 256 + ko);
                }
#pragma unroll
                for (int kk = 0; kk < 32; kk++) {
                    float2 avv = *(const float2*)&sX[kk][tm];
                    float2 bvv = *(const float2*)&sW[kk][tn];
                    a00 = fmaf(avv.x, bvv.x, a00);
                    a01 = fmaf(avv.x, bvv.y, a01);
                    a10 = fmaf(avv.y, bvv.x, a10);
                    a11 = fmaf(avv.y, bvv.y, a11);
                }
            }
            __syncthreads();
            const int m = m0 + tm, n = n0 + tn;
            if (z == 0) {
#define AIDX(m_, n_) ((((m_) >> 7) * 4 + ((n_) >> 6)) * 8192 + ((m_) & 127) * 64 + ((n_) & 63))
                g_Achunk[AIDX(m, n)]         = a00;
                g_Achunk[AIDX(m, n + 1)]     = a01;
                g_Achunk[AIDX(m + 1, n)]     = a10;
                g_Achunk[AIDX(m + 1, n + 1)] = a11;
#undef AIDX
            } else {
                g_B[m * 256 + n] = a00;       g_B[m * 256 + n + 1] = a01;
                g_B[(m + 1) * 256 + n] = a10; g_B[(m + 1) * 256 + n + 1] = a11;
            }
        }
    }
    grid_sync(&g_sync1);

    // =============== PHASE 2: pair (round-14 body; Bm via __ldcg) ===============
    {
        const int wm = w >> 2;
        const int wn = w & 3;

        int nu = 0;
        for (int uu = bid; uu < 1024; uu += NCTA) nu++;
        const int nchunks = nu * 8;

        float* sBB = (float*)(smp + OFF_BB);
        const uint32_t mbA  = sb + OFF_MB + 0;
        const uint32_t mbW0 = sb + OFF_MB + 8;
        const uint32_t mbW1 = sb + OFF_MB + 16;

        // __ldcg: coherent L2 load (g_B written this kernel; nc path forbidden)
        sBB[t] = __ldcg(&g_B[(bid & 511) * 256 + t]) + bf1[t];
        if (t == 0) {
            MBARRIER_INIT(mbA, 1);
            MBARRIER_INIT(mbW0, 1); MBARRIER_INIT(mbW1, 1);
        }

        const uint32_t lx = (uint32_t)(lane & 7) * 16u;
        const uint32_t rowOff = (uint32_t)(lane & 15) * 128u;
        const uint32_t segOff = (uint32_t)(lane >> 4) * 16u;
        const uint32_t wmOff = (uint32_t)(wm * 64) * 128u + rowOff;
        const uint32_t wnOff = (uint32_t)(wn * 64) * 128u + rowOff;

        float s[16];
#pragma unroll
        for (int q = 0; q < 16; q++) s[q] = 0.f;

        float acc[4][8][4];
#pragma unroll
        for (int mt = 0; mt < 4; mt++)
#pragma unroll
            for (int nt = 0; nt < 8; nt++)
#pragma unroll
                for (int e = 0; e < 4; e++) acc[mt][nt][e] = 0.f;

        uint32_t ap = 0, wp0 = 0, wp1 = 0;

#define STAGE_BULKS(cx_) do { \
        const int c_ = (cx_) & 7; \
        const int u_ = bid + ((cx_) >> 3) * NCTA; \
        const int kc_ = c_ & 3; \
        const int it_ = (u_ >> 9) * 2 + (c_ >> 2); \
        const int wb_ = (cx_) & 1; \
        const uint32_t mbw_ = wb_ ? mbW1 : mbW0; \
        MBARRIER_EXPECT_TX(mbA, 32768u); \
        CP_BULK(sb + OFF_RAW, (const void*)(g_Achunk + (it_ * 4 + kc_) * 8192), 32768u, mbA); \
        MBARRIER_EXPECT_TX(mbw_, 65536u); \
        CP_BULK(sb + OFF_WHI + (uint32_t)wb_ * 32768u, (const void*)(g_Whi4 + kc_ * 2048), 32768u, mbw_); \
        CP_BULK(sb + OFF_WLO + (uint32_t)wb_ * 32768u, (const void*)(g_Wlo4 + kc_ * 2048), 32768u, mbw_); \
    } while (0)

#define CONV_ONE(r_) do { \
        const int li = (r_) * 256 + t; \
        const int row_ = li >> 4, seg_ = li & 15; \
        float4 v = *(const float4*)(rawp + li * 4); \
        float4 bbv = *(const float4*)(bbp + seg_ * 4); \
        float f0 = fmaxf(v.x + bbv.x, 0.f), f1 = fmaxf(v.y + bbv.y, 0.f); \
        float f2 = fmaxf(v.z + bbv.z, 0.f), f3 = fmaxf(v.w + bbv.w, 0.f); \
        uint2 hp, lp; \
        hp.x = pack_rn2(f0, f1); hp.y = pack_rn2(f2, f3); \
        lp.x = pack_rn2(f0 - __uint_as_float(hp.x << 16), \
                        f1 - __uint_as_float(hp.x & 0xFFFF0000u)); \
        lp.y = pack_rn2(f2 - __uint_as_float(hp.y << 16), \
                        f3 - __uint_as_float(hp.y & 0xFFFF0000u)); \
        const uint32_t off_ = (uint32_t)(row_ * 128 + seg_ * 8); \
        const uint32_t sw = off_ ^ ((uint32_t)(row_ & 7) * 16u); \
        *(uint2*)(aHi + sw) = hp; \
        *(uint2*)(aLo + sw) = lp; \
    } while (0)

        __syncthreads();
        if (t == 0) STAGE_BULKS(0);
        MBARRIER_WAIT_PARITY(mbA, ap); ap ^= 1;
        {
            const float* rawp = (const float*)(smp + OFF_RAW);
            char* aHi = smp + OFF_AHI;
            char* aLo = smp + OFF_ALO;
            const float* bbp = sBB + 0;
#pragma unroll
            for (int r = 0; r < 8; r++) CONV_ONE(r);
        }
        MBARRIER_WAIT_PARITY(mbW0, wp0); wp0 ^= 1;
        __syncthreads();

#pragma unroll 1
        for (int ci = 0; ci < nchunks; ci++) {
            const int c = ci & 7;
            const int ui = ci >> 3;
            const int b = ci & 1;
            const bool cvt = (ci + 1 < nchunks);

            if (cvt && t == 0) STAGE_BULKS(ci + 1);

            if (c == 0 && ui + 1 < nu) {
                const int jn = (bid + (ui + 1) * NCTA) & 511;
                sBB[((ui + 1) & 1) * 256 + t] = __ldcg(&g_B[jn * 256 + t]) + bf1[t];
            }

            const float* rawp = (const float*)(smp + OFF_RAW);
            char* aHi = smp + OFF_AHI + (uint32_t)(b ^ 1) * 16384u;
            char* aLo = smp + OFF_ALO + (uint32_t)(b ^ 1) * 16384u;
            const int ci2 = ci + 1;
            const float* bbp = sBB + ((ci2 >> 3) & 1) * 256 + ((ci2 & 3) * 64);

            {
                const uint32_t aRowHi = sb + OFF_AHI + (uint32_t)b * 16384u + wmOff;
                const uint32_t aRowLo = sb + OFF_ALO + (uint32_t)b * 16384u + wmOff;
                const uint32_t wRowHi = sb + OFF_WHI + (uint32_t)b * 32768u + wnOff;
                const uint32_t wRowLo = sb + OFF_WLO + (uint32_t)b * 32768u + wnOff;
#pragma unroll
                for (int ks = 0; ks < 4; ks++) {
                    const uint32_t kx = ((uint32_t)(ks * 32) + segOff) ^ lx;
                    uint32_t aH[4][4], aL[4][4], wf[4][4];
#pragma unroll
                    for (int mt = 0; mt < 4; mt++) ldsm4(aH[mt], aRowHi + mt * 2048 + kx);
#pragma unroll
                    for (int np = 0; np < 4; np++) ldsm4(wf[np], wRowHi + np * 2048 + kx);
#pragma unroll
                    for (int mt = 0; mt < 4; mt++)
#pragma unroll
                        for (int np = 0; np < 4; np++) {
                            mma16816(acc[mt][2 * np],     aH[mt], wf[np][0], wf[np][2]);
                            mma16816(acc[mt][2 * np + 1], aH[mt], wf[np][1], wf[np][3]);
                        }
                    if (ks == 1 && cvt) { MBARRIER_WAIT_PARITY(mbA, ap); ap ^= 1; CONV_ONE(0); }
                    if (ks == 2 && cvt) { CONV_ONE(3); }
                    if (ks == 3 && cvt) { CONV_ONE(6); }
#pragma unroll
                    for (int mt = 0; mt < 4; mt++) ldsm4(aL[mt], aRowLo + mt * 2048 + kx);
#pragma unroll
                    for (int mt = 0; mt < 4; mt++)
#pragma unroll
                        for (int np = 0; np < 4; np++) {
                            mma16816(acc[mt][2 * np],     aL[mt], wf[np][0], wf[np][2]);
                            mma16816(acc[mt][2 * np + 1], aL[mt], wf[np][1], wf[np][3]);
                        }
                    if (ks == 1 && cvt) { CONV_ONE(1); }
                    if (ks == 2 && cvt) { CONV_ONE(4); }
                    if (ks == 3 && cvt) { CONV_ONE(7); }
#pragma unroll
                    for (int np = 0; np < 4; np++) ldsm4(wf[np], wRowLo + np * 2048 + kx);
#pragma unroll
                    for (int mt = 0; mt < 4; mt++)
#pragma unroll
                        for (int np = 0; np < 4; np++) {
                            mma16816(acc[mt][2 * np],     aH[mt], wf[np][0], wf[np][2]);
                            mma16816(acc[mt][2 * np + 1], aH[mt], wf[np][1], wf[np][3]);
                        }
                    if (ks == 1 && cvt) { CONV_ONE(2); }
                    if (ks == 2 && cvt) { CONV_ONE(5); }
                }
            }

            if ((c & 3) == 3) {
#pragma unroll
                for (int nt = 0; nt < 8; nt++) {
                    const int col = wn * 64 + nt * 8 + (lane & 3) * 2;
                    const float b20 = bf2[col], b21 = bf2[col + 1];
                    float t0 = 0.f, t1 = 0.f;
#pragma unroll
                    for (int mt = 0; mt < 4; mt++) {
                        t0 += fmaxf(acc[mt][nt][0] + b20, 0.f) + fmaxf(acc[mt][nt][2] + b20, 0.f);
                        t1 += fmaxf(acc[mt][nt][1] + b21, 0.f) + fmaxf(acc[mt][nt][3] + b21, 0.f);
                        acc[mt][nt][0] = 0.f; acc[mt][nt][1] = 0.f;
                        acc[mt][nt][2] = 0.f; acc[mt][nt][3] = 0.f;
                    }
                    s[nt * 2]     += t0;
                    s[nt * 2 + 1] += t1;
                }
            }

            if (c == 7) {
                const int u = bid + ui * NCTA;
                const int j = u & 511, half = u >> 9;
#pragma unroll
                for (int q = 0; q < 16; q++) {
                    s[q] += __shfl_xor_sync(0xFFFFFFFFu, s[q], 4);
                    s[q] += __shfl_xor_sync(0xFFFFFFFFu, s[q], 8);
                    s[q] += __shfl_xor_sync(0xFFFFFFFFu, s[q], 16);
                }
                if (lane < 4) {
                    float* dst = g_S2p[half * 2 + wm] + j * 256;
#pragma unroll
                    for (int nt = 0; nt < 8; nt++) {
                        const int col = wn * 64 + nt * 8 + lane * 2;
                        dst[col]     = s[nt * 2];
                        dst[col + 1] = s[nt * 2 + 1];
                    }
                }
#pragma unroll
                for (int q = 0; q < 16; q++) s[q] = 0.f;
            }

            if (cvt) {
                if (ci2 & 1) { MBARRIER_WAIT_PARITY(mbW1, wp1); wp1 ^= 1; }
                else         { MBARRIER_WAIT_PARITY(mbW0, wp0); wp0 ^= 1; }
            }
            __syncthreads();
        }
    }
    grid_sync(&g_sync2);

    // =============== PHASE 3: tail (CTAs 0..127) ===============
    if (bid < 128) {
        float* Xa = (float*)(smp);
        float* Xb = (float*)(smp + 8192);
        const int ng = lane >> 3, kl = lane & 7;
        const int r0 = bid * 4;

#pragma unroll
        for (int r = 0; r < 4; r++) {
            const int gi = (r0 + r) * 256 + t;
            Xa[r * 512 + t] = __ldcg(&g_S2p[0][gi]) + __ldcg(&g_S2p[1][gi])
                            + __ldcg(&g_S2p[2][gi]) + __ldcg(&g_S2p[3][gi]);
        }
        __syncthreads();

#pragma unroll
        for (int q = 0; q < 2; q++) {
            const int item = q * 256 + t;
            const int r = item >> 7, k = item & 127;
            Xb[r * 512 + k] = x[(r0 + r) * 128 + k];
        }
        wlayer<256, 128, 0>(Xa, Wf3, bf3, 512.f, Xb + 128, w, ng, kl);
        __syncthreads();

        wlayer<256, 256, 1>(Xb, Wg1, bg1, 1.f, Xa, w, ng, kl);
        __syncthreads();

        wlayer<256, 256, 1>(Xa, Wg2, bg2, 1.f, Xb, w, ng, kl);
        __syncthreads();

#pragma unroll
        for (int q = 0; q < 2; q++) {
            const int item = q * 256 + t;
            const int r = item >> 7, k = item & 127;
            Xa[r * 512 + 128 + k] = h0[(r0 + r) * 128 + k];
        }
        wlayer<256, 128, 0>(Xb, Wg3, bg3, 1.f, Xa, w, ng, kl);
        __syncthreads();

        wlayer_gates(Xa, W_ih, W_hh, b_ih, b_hh, Xb, w, ng, kl);
        __syncthreads();

#pragma unroll
        for (int q = 0; q < 2; q++) {
            const int item = q * 256 + t;
            const int r = item >> 7, h = item & 127;
            const float* g = Xb + r * 512;
            const float ig = 1.f / (1.f + expf(-g[h]));
            const float fg = 1.f / (1.f + expf(-g[128 + h]));
            const float gg = tanhf(g[256 + h]);
            const float og = 1.f / (1.f + expf(-g[384 + h]));
            const int gi = (r0 + r) * 128 + h;
            const float c = fg * c0[gi] + ig * gg;
            const float hn = og * tanhf(c);
            Xa[r * 512 + h] = hn;
            out[32768 + gi]  = hn;
            out[98304 + gi]  = hn;
            out[163840 + gi] = c;
        }
        __syncthreads();

        wlayer<128, 256, 1>(Xa, Wo1, bo1, 1.f, Xb, w, ng, kl);
        __syncthreads();

#pragma unroll
        for (int it = 0; it < 2; it++) {
            const int n = it * 32 + w * 4 + ng;
            const float* wr = Wo2 + n * 256 + kl * 4;
            float a0 = 0.f, a1 = 0.f, a2 = 0.f, a3 = 0.f;
#pragma unroll
            for (int jj = 0; jj < 8; jj++) {
                const int k = kl * 4 + jj * 32;
                const float4 wv = *(const float4*)(wr + jj * 32);
                const float4 x0 = *(const float4*)(Xb + 0 * 512 + k);
                const float4 x1 = *(const float4*)(Xb + 1 * 512 + k);
                const float4 x2 = *(const float4*)(Xb + 2 * 512 + k);
                const float4 x3 = *(const float4*)(Xb + 3 * 512 + k);
                a0 += wv.x * x0.x + wv.y * x0.y + wv.z * x0.z + wv.w * x0.w;
                a1 += wv.x * x1.x + wv.y * x1.y + wv.z * x1.z + wv.w * x1.w;
                a2 += wv.x * x2.x + wv.y * x2.y + wv.z * x2.z + wv.w * x2.w;
                a3 += wv.x * x3.x + wv.y * x3.y + wv.z * x3.z + wv.w * x3.w;
            }
#pragma unroll
            for (int m = 1; m < 8; m <<= 1) {
                a0 += __shfl_xor_sync(0xFFFFFFFFu, a0, m);
                a1 += __shfl_xor_sync(0xFFFFFFFFu, a1, m);
                a2 += __shfl_xor_sync(0xFFFFFFFFu, a2, m);
                a3 += __shfl_xor_sync(0xFFFFFFFFu, a3, m);
            }
            if (kl == 0) {
                const float bb = bo2[n];
                out[(r0 + 0) * 64 + n] = a0 + bb;
                out[(r0 + 1) * 64 + n] = a1 + bb;
                out[(r0 + 2) * 64 + n] = a2 + bb;
                out[(r0 + 3) * 64 + n] = a3 + bb;
            }
        }
    }
}

// ---------------- launch ----------------
extern "C" void kernel_launch(void* const* d_in, const int* in_sizes, int n_in,
                              void* d_out, int out_size)
{
    const float* x    = (const float*)d_in[0];
    const float* hid  = (const float*)d_in[1];
    const float* h0   = (const float*)d_in[2];
    const float* c0   = (const float*)d_in[3];
    const float* Wf1  = (const float*)d_in[4];
    const float* bf1  = (const float*)d_in[5];
    const float* Wf2  = (const float*)d_in[6];
    const float* bf2  = (const float*)d_in[7];
    const float* Wf3  = (const float*)d_in[8];
    const float* bf3  = (const float*)d_in[9];
    const float* Wg1  = (const float*)d_in[10];
    const float* bg1  = (const float*)d_in[11];
    const float* Wg2  = (const float*)d_in[12];
    const float* bg2  = (const float*)d_in[13];
    const float* Wg3  = (const float*)d_in[14];
    const float* bg3  = (const float*)d_in[15];
    const float* W_ih = (const float*)d_in[16];
    const float* W_hh = (const float*)d_in[17];
    const float* b_ih = (const float*)d_in[18];
    const float* b_hh = (const float*)d_in[19];
    const float* Wo1  = (const float*)d_in[20];
    const float* bo1  = (const float*)d_in[21];
    const float* Wo2  = (const float*)d_in[22];
    const float* bo2  = (const float*)d_in[23];
    float* out = (float*)d_out;

    cudaFuncSetAttribute(mega_kernel, cudaFuncAttributeMaxDynamicSharedMemorySize, MEGA_DYN_SMEM);

    mega_kernel<<<NCTA, 256, MEGA_DYN_SMEM>>>(
        x, hid, h0, c0, Wf1, bf1, Wf2, bf2, Wf3, bf3,
        Wg1, bg1, Wg2, bg2, Wg3, bg3, W_ih, W_hh, b_ih, b_hh,
        Wo1, bo1, Wo2, bo2, out);
}